// round 4
// baseline (speedup 1.0000x reference)
#include <cuda_runtime.h>

// Problem constants
#define NB   8          // batch
#define NC   256        // channels
#define NM   128        // m = C/2
#define NPIX 16384      // N = H*W
#define EPSV 1e-6f

// ---------------- scratch (static device arrays; no allocation) ----------------
__device__ float g_QKV[(size_t)NB * 512 * NPIX];   // rows 0-127 Q, 128-255 K, 256-511 V
__device__ float g_invQ[NB * NPIX];
__device__ float g_invK[NB * NPIX];
__device__ float g_Ksum[NB * NM];
__device__ float g_vsum[NB * NC];
__device__ float g_matrix[NB * NM * NC];           // [b][m][C]
__device__ float g_tailor[NB * NPIX];

// ---------------- tf32 helpers ----------------
__device__ __forceinline__ float tf32r(float f) {
    unsigned u;
    asm("cvt.rna.tf32.f32 %0, %1;" : "=r"(u) : "f"(f));
    return __uint_as_float(u);
}
__device__ __forceinline__ void mma_tf32(float* d, const unsigned* a,
                                         const unsigned* b) {
    asm volatile(
        "mma.sync.aligned.m16n8k8.row.col.f32.tf32.tf32.f32 "
        "{%0,%1,%2,%3}, {%4,%5,%6,%7}, {%8,%9}, {%0,%1,%2,%3};"
        : "+f"(d[0]), "+f"(d[1]), "+f"(d[2]), "+f"(d[3])
        : "r"(a[0]), "r"(a[1]), "r"(a[2]), "r"(a[3]), "r"(b[0]), "r"(b[1]));
}

#define SMS 132   // smem row stride (128 + 4): stride mod 32 == 4 -> conflict-free frags

// ---------------- zero accumulators (graph-replay determinism) ----------------
__global__ void zero_kernel() {
    const int total = NB*NM + NB*NC + NB*NM*NC;
    for (int i = blockIdx.x * blockDim.x + threadIdx.x; i < total;
         i += gridDim.x * blockDim.x) {
        if (i < NB*NM)            g_Ksum[i] = 0.f;
        else if (i < NB*NM+NB*NC) g_vsum[i - NB*NM] = 0.f;
        else                      g_matrix[i - NB*NM - NB*NC] = 0.f;
    }
}

// compute 16 MMAs for one BK=32 smem stage (4 ksteps), warp tile 32x64
__device__ __forceinline__ void mma_stage(const float (*As)[SMS],
                                          const float (*Bs)[SMS],
                                          float acc[2][8][4],
                                          int warp_m, int warp_n, int lane) {
    const int lq = lane & 3, lr = lane >> 2;
    #pragma unroll
    for (int kk = 0; kk < 4; kk++) {
        const int k0 = kk * 8 + lq;
        unsigned afr[2][4], bfr[8][2];
        #pragma unroll
        for (int i = 0; i < 2; i++) {
            int mr = warp_m * 32 + i * 16 + lr;
            afr[i][0] = __float_as_uint(As[k0][mr]);
            afr[i][1] = __float_as_uint(As[k0][mr + 8]);
            afr[i][2] = __float_as_uint(As[k0 + 4][mr]);
            afr[i][3] = __float_as_uint(As[k0 + 4][mr + 8]);
        }
        #pragma unroll
        for (int j = 0; j < 8; j++) {
            int nc = warp_n * 64 + j * 8 + lr;
            bfr[j][0] = __float_as_uint(Bs[k0][nc]);
            bfr[j][1] = __float_as_uint(Bs[k0 + 4][nc]);
        }
        #pragma unroll
        for (int i = 0; i < 2; i++)
            #pragma unroll
            for (int j = 0; j < 8; j++)
                mma_tf32(acc[i][j], afr[i], bfr[j]);
    }
}

// ---------------- GEMM1: QKV = [Wq;Wk;Wv] @ x + bias (tf32 tensor) ----------------
// grid (NPIX/128, 4, NB), 256 thr
__global__ __launch_bounds__(256) void gemm_qkv(
    const float* __restrict__ x,
    const float* __restrict__ Wq, const float* __restrict__ bq,
    const float* __restrict__ Wk, const float* __restrict__ bk,
    const float* __restrict__ Wv, const float* __restrict__ bv)
{
    const int b  = blockIdx.z;
    const int mt = blockIdx.y;     // 0:Q 1:K 2,3:V halves
    const int nblk = blockIdx.x;

    const float *W, *bias; int wrow0;
    if (mt == 0)      { W = Wq; bias = bq; wrow0 = 0; }
    else if (mt == 1) { W = Wk; bias = bk; wrow0 = 0; }
    else              { W = Wv; bias = bv; wrow0 = (mt - 2) * 128; }

    __shared__ float As[32][SMS];   // [k][m]
    __shared__ float Bs[32][SMS];   // [k][n]

    const int tid = threadIdx.x, lane = tid & 31, wid = tid >> 5;
    const int warp_m = wid & 3, warp_n = wid >> 2;
    const int n0 = nblk * 128;
    const float* xb = x + (size_t)b * NC * NPIX;

    // load indices
    const int aq = (tid & 7) * 4, am = tid >> 3;          // A: k-quad, m-row
    const int bn = (tid & 31) * 4, bkr = tid >> 5;        // B: n-quad, k-row

    float acc[2][8][4] = {};
    float4 pa[4], pb[4];

    // prefetch iter 0
    #pragma unroll
    for (int s = 0; s < 4; s++) {
        pa[s] = *reinterpret_cast<const float4*>(
            &W[(size_t)(wrow0 + am + 32 * s) * NC + aq]);
        pb[s] = *reinterpret_cast<const float4*>(
            &xb[(size_t)(bkr + 8 * s) * NPIX + n0 + bn]);
    }

    for (int it = 0; it < 8; ++it) {
        #pragma unroll
        for (int s = 0; s < 4; s++) {
            As[aq + 0][am + 32 * s] = tf32r(pa[s].x);
            As[aq + 1][am + 32 * s] = tf32r(pa[s].y);
            As[aq + 2][am + 32 * s] = tf32r(pa[s].z);
            As[aq + 3][am + 32 * s] = tf32r(pa[s].w);
            float4 v = pb[s];
            v.x = tf32r(v.x); v.y = tf32r(v.y); v.z = tf32r(v.z); v.w = tf32r(v.w);
            *reinterpret_cast<float4*>(&Bs[bkr + 8 * s][bn]) = v;
        }
        __syncthreads();
        if (it + 1 < 8) {
            const int kt = (it + 1) * 32;
            #pragma unroll
            for (int s = 0; s < 4; s++) {
                pa[s] = *reinterpret_cast<const float4*>(
                    &W[(size_t)(wrow0 + am + 32 * s) * NC + kt + aq]);
                pb[s] = *reinterpret_cast<const float4*>(
                    &xb[(size_t)(kt + bkr + 8 * s) * NPIX + n0 + bn]);
            }
        }
        mma_stage(As, Bs, acc, warp_m, warp_n, lane);
        __syncthreads();
    }

    // epilogue: bias, store
    float* out = g_QKV + ((size_t)b * 512 + (size_t)mt * 128) * NPIX;
    const int lq = lane & 3, lr = lane >> 2;
    #pragma unroll
    for (int i = 0; i < 2; i++) {
        int r0 = warp_m * 32 + i * 16 + lr;
        float b0 = bias[wrow0 + r0], b1 = bias[wrow0 + r0 + 8];
        #pragma unroll
        for (int j = 0; j < 8; j++) {
            int ncol = n0 + warp_n * 64 + j * 8 + 2 * lq;
            *reinterpret_cast<float2*>(&out[(size_t)r0 * NPIX + ncol]) =
                make_float2(acc[i][j][0] + b0, acc[i][j][1] + b0);
            *reinterpret_cast<float2*>(&out[(size_t)(r0 + 8) * NPIX + ncol]) =
                make_float2(acc[i][j][2] + b1, acc[i][j][3] + b1);
        }
    }
}

// ---------------- per-pixel inverse channel norms of Q and K ----------------
__global__ void norms_kernel() {
    const int b = blockIdx.y;
    const int n = blockIdx.x * 256 + threadIdx.x;
    const float* Qb = g_QKV + (size_t)b * 512 * NPIX;
    const float* Kb = Qb + (size_t)128 * NPIX;
    float sq = 0.f, sk = 0.f;
    for (int c = 0; c < NM; c++) {
        float q = Qb[(size_t)c * NPIX + n]; sq = fmaf(q, q, sq);
        float k = Kb[(size_t)c * NPIX + n]; sk = fmaf(k, k, sk);
    }
    g_invQ[b * NPIX + n] = rsqrtf(sq);
    g_invK[b * NPIX + n] = rsqrtf(sk);
}

// ---------------- GEMM2: matrix[m][C] += Kn @ V^T over pixel chunks + Ksum/vsum --
// grid (16 chunks, 2 ch, NB), 256 thr, each block reduces 1024 pixels
__global__ __launch_bounds__(256) void gemm_kv() {
    const int chunk = blockIdx.x, ch = blockIdx.y, b = blockIdx.z;

    __shared__ float As[32][SMS];   // [npix_loc][m]  (Kn, A role: row=m, k=n)
    __shared__ float Bs[32][SMS];   // [npix_loc][c]  (V^T, B role)
    __shared__ float redm[128], redc[128];

    const int tid = threadIdx.x, lane = tid & 31, wid = tid >> 5;
    const int warp_m = wid & 3, warp_n = wid >> 2;

    const float* Kb = g_QKV + ((size_t)b * 512 + 128) * NPIX;
    const float* Vb = g_QKV + ((size_t)b * 512 + 256 + (size_t)ch * 128) * NPIX;
    const float* iK = g_invK + b * NPIX;
    const int n0 = chunk * 1024;

    const int aq = (tid & 7) * 4, am = tid >> 3;     // A: n-quad, m-row (0..31)
    const int vc = tid & 127, vg = (tid >> 7) * 16;  // B: c, n-halfgroup

    float acc[2][8][4] = {};
    float ksacc[4] = {}, vsacc = 0.f;
    float4 pa[4], pik, pb[4];

    // prefetch iter 0
    pik = *reinterpret_cast<const float4*>(&iK[n0 + aq]);
    #pragma unroll
    for (int s = 0; s < 4; s++) {
        pa[s] = *reinterpret_cast<const float4*>(
            &Kb[(size_t)(am + 32 * s) * NPIX + n0 + aq]);
        pb[s] = *reinterpret_cast<const float4*>(
            &Vb[(size_t)vc * NPIX + n0 + vg + 4 * s]);
    }

    for (int it = 0; it < 32; ++it) {
        #pragma unroll
        for (int s = 0; s < 4; s++) {
            float4 k4 = pa[s];
            k4.x *= pik.x; k4.y *= pik.y; k4.z *= pik.z; k4.w *= pik.w;
            ksacc[s] += k4.x + k4.y + k4.z + k4.w;
            As[aq + 0][am + 32 * s] = tf32r(k4.x);
            As[aq + 1][am + 32 * s] = tf32r(k4.y);
            As[aq + 2][am + 32 * s] = tf32r(k4.z);
            As[aq + 3][am + 32 * s] = tf32r(k4.w);
            float4 v4 = pb[s];
            vsacc += v4.x + v4.y + v4.z + v4.w;
            Bs[vg + 4 * s + 0][vc] = tf32r(v4.x);
            Bs[vg + 4 * s + 1][vc] = tf32r(v4.y);
            Bs[vg + 4 * s + 2][vc] = tf32r(v4.z);
            Bs[vg + 4 * s + 3][vc] = tf32r(v4.w);
        }
        __syncthreads();
        if (it + 1 < 32) {
            const int nb_ = n0 + (it + 1) * 32;
            pik = *reinterpret_cast<const float4*>(&iK[nb_ + aq]);
            #pragma unroll
            for (int s = 0; s < 4; s++) {
                pa[s] = *reinterpret_cast<const float4*>(
                    &Kb[(size_t)(am + 32 * s) * NPIX + nb_ + aq]);
                pb[s] = *reinterpret_cast<const float4*>(
                    &Vb[(size_t)vc * NPIX + nb_ + vg + 4 * s]);
            }
        }
        mma_stage(As, Bs, acc, warp_m, warp_n, lane);
        __syncthreads();
    }

    // matrix partials -> global atomics
    float* mb = g_matrix + (size_t)b * NM * NC + ch * 128;
    const int lq = lane & 3, lr = lane >> 2;
    #pragma unroll
    for (int i = 0; i < 2; i++) {
        int r0 = warp_m * 32 + i * 16 + lr;
        #pragma unroll
        for (int j = 0; j < 8; j++) {
            int col = warp_n * 64 + j * 8 + 2 * lq;
            atomicAdd(&mb[(size_t)r0 * NC + col],       acc[i][j][0]);
            atomicAdd(&mb[(size_t)r0 * NC + col + 1],   acc[i][j][1]);
            atomicAdd(&mb[(size_t)(r0+8) * NC + col],   acc[i][j][2]);
            atomicAdd(&mb[(size_t)(r0+8) * NC + col+1], acc[i][j][3]);
        }
    }

    // Ksum / vsum reductions
    if (tid < 128) { redm[tid] = 0.f; redc[tid] = 0.f; }
    __syncthreads();
    #pragma unroll
    for (int s = 0; s < 4; s++) atomicAdd(&redm[am + 32 * s], ksacc[s]);
    atomicAdd(&redc[vc], vsacc);
    __syncthreads();
    if (tid < 128) {
        atomicAdd(&g_vsum[b * NC + ch * 128 + tid], redc[tid]);
        if (ch == 0) atomicAdd(&g_Ksum[b * NM + tid], redm[tid]);
    }
}

// ---------------- tailor[n] = 1/(N + Qn . (Ksum + eps)) ----------------
__global__ void tailor_kernel() {
    __shared__ float ks[128];
    const int b = blockIdx.y;
    const int n = blockIdx.x * 256 + threadIdx.x;
    if (threadIdx.x < 128) ks[threadIdx.x] = g_Ksum[b * NM + threadIdx.x] + EPSV;
    __syncthreads();
    const float* Qb = g_QKV + (size_t)b * 512 * NPIX;
    float dot = 0.f;
    for (int c = 0; c < NM; c++)
        dot = fmaf(Qb[(size_t)c * NPIX + n], ks[c], dot);
    g_tailor[b * NPIX + n] =
        1.0f / ((float)NPIX + g_invQ[b * NPIX + n] * dot);
}

// ---------------- GEMM3: out[c,n] = g*tailor[n]*(vsum[c] + matrix^T @ Qn) ----------
// grid (NPIX/128, 2, NB), 256 thr, K = 128
__global__ __launch_bounds__(256) void gemm_out(
    const float* __restrict__ gamma, float* __restrict__ out)
{
    const int nblk = blockIdx.x, ch = blockIdx.y, b = blockIdx.z;

    __shared__ float As[32][SMS];   // [m_loc][c]
    __shared__ float Bs[32][SMS];   // [m_loc][n]
    __shared__ float stl[128], svs[128];

    const int tid = threadIdx.x, lane = tid & 31, wid = tid >> 5;
    const int warp_m = wid & 3, warp_n = wid >> 2;
    const int n0 = nblk * 128;

    const float* Qb  = g_QKV + (size_t)b * 512 * NPIX;
    const float* iQ  = g_invQ + b * NPIX;
    const float* mat = g_matrix + (size_t)b * NM * NC + ch * 128;

    const int acq = (tid & 31) * 4, amr = tid >> 5;   // A: c-quad, m-row (0..7)
    const int bn4 = (tid & 31) * 4, bmr = tid >> 5;   // B: n-quad, m-row

    if (tid < 128) {
        stl[tid] = gamma[0] * g_tailor[b * NPIX + n0 + tid];
        svs[tid] = g_vsum[b * NC + ch * 128 + tid];
    }

    float4 piq = *reinterpret_cast<const float4*>(&iQ[n0 + bn4]);
    float acc[2][8][4] = {};
    float4 pa[4], pb[4];

    #pragma unroll
    for (int s = 0; s < 4; s++) {
        pa[s] = *reinterpret_cast<const float4*>(
            &mat[(size_t)(amr + 8 * s) * NC + acq]);
        pb[s] = *reinterpret_cast<const float4*>(
            &Qb[(size_t)(bmr + 8 * s) * NPIX + n0 + bn4]);
    }

    for (int it = 0; it < 4; ++it) {
        #pragma unroll
        for (int s = 0; s < 4; s++) {
            float4 a4 = pa[s];
            a4.x = tf32r(a4.x); a4.y = tf32r(a4.y);
            a4.z = tf32r(a4.z); a4.w = tf32r(a4.w);
            *reinterpret_cast<float4*>(&As[amr + 8 * s][acq]) = a4;
            float4 q4 = pb[s];
            q4.x = tf32r(q4.x * piq.x); q4.y = tf32r(q4.y * piq.y);
            q4.z = tf32r(q4.z * piq.z); q4.w = tf32r(q4.w * piq.w);
            *reinterpret_cast<float4*>(&Bs[bmr + 8 * s][bn4]) = q4;
        }
        __syncthreads();
        if (it + 1 < 4) {
            const int m0 = (it + 1) * 32;
            #pragma unroll
            for (int s = 0; s < 4; s++) {
                pa[s] = *reinterpret_cast<const float4*>(
                    &mat[(size_t)(m0 + amr + 8 * s) * NC + acq]);
                pb[s] = *reinterpret_cast<const float4*>(
                    &Qb[(size_t)(m0 + bmr + 8 * s) * NPIX + n0 + bn4]);
            }
        }
        mma_stage(As, Bs, acc, warp_m, warp_n, lane);
        __syncthreads();
    }

    float* ob = out + ((size_t)b * NC + (size_t)ch * 128) * NPIX;
    const int lq = lane & 3, lr = lane >> 2;
    #pragma unroll
    for (int i = 0; i < 2; i++) {
        int r0 = warp_m * 32 + i * 16 + lr;
        float v0 = svs[r0], v1 = svs[r0 + 8];
        #pragma unroll
        for (int j = 0; j < 8; j++) {
            int ncl = warp_n * 64 + j * 8 + 2 * lq;
            float t0 = stl[ncl], t1 = stl[ncl + 1];
            *reinterpret_cast<float2*>(&ob[(size_t)r0 * NPIX + n0 + ncl]) =
                make_float2(t0 * (v0 + acc[i][j][0]), t1 * (v0 + acc[i][j][1]));
            *reinterpret_cast<float2*>(&ob[(size_t)(r0 + 8) * NPIX + n0 + ncl]) =
                make_float2(t0 * (v1 + acc[i][j][2]), t1 * (v1 + acc[i][j][3]));
        }
    }
}

// ---------------- launch ----------------
extern "C" void kernel_launch(void* const* d_in, const int* in_sizes, int n_in,
                              void* d_out, int out_size)
{
    const float* x     = (const float*)d_in[0];
    const float* Wq    = (const float*)d_in[1];
    const float* bq    = (const float*)d_in[2];
    const float* Wk    = (const float*)d_in[3];
    const float* bk    = (const float*)d_in[4];
    const float* Wv    = (const float*)d_in[5];
    const float* bv    = (const float*)d_in[6];
    const float* gamma = (const float*)d_in[7];
    float* out = (float*)d_out;

    zero_kernel<<<64, 256>>>();
    gemm_qkv<<<dim3(NPIX / 128, 4, NB), 256>>>(x, Wq, bq, Wk, bk, Wv, bv);
    norms_kernel<<<dim3(NPIX / 256, NB), 256>>>();
    gemm_kv<<<dim3(16, 2, NB), 256>>>();
    tailor_kernel<<<dim3(NPIX / 256, NB), 256>>>();
    gemm_out<<<dim3(NPIX / 128, 2, NB), 256>>>(gamma, out);
}

// round 6
// speedup vs baseline: 1.5122x; 1.5122x over previous
#include <cuda_runtime.h>
#include <cstdint>

#define NB 8
#define NC 256
#define NM 128
#define NPIX 16384
#define EPSV 1e-6f

// ---------------- scratch ----------------
__device__ float g_QKV[(size_t)NB*512*NPIX];  // 0-127 Qn, 128-255 Kn, 256-511 V (post-epilogue)
__device__ float g_Ksum[NB*NM];
__device__ float g_vsum[NB*NC];
__device__ float g_matT[(size_t)NB*NC*NM];    // [b][c][m]
__device__ float g_tailor[NB*NPIX];

__device__ __forceinline__ unsigned smem_u32(const void* p){
    unsigned a; asm("{ .reg .u64 t; cvta.to.shared.u64 t, %1; cvt.u32.u64 %0, t; }":"=r"(a):"l"(p)); return a;
}
__device__ __forceinline__ void mma_tf32(float* d, const unsigned* a, const unsigned* b){
    asm volatile("mma.sync.aligned.m16n8k8.row.col.f32.tf32.tf32.f32 "
        "{%0,%1,%2,%3}, {%4,%5,%6,%7}, {%8,%9}, {%0,%1,%2,%3};"
        : "+f"(d[0]), "+f"(d[1]), "+f"(d[2]), "+f"(d[3])
        : "r"(a[0]), "r"(a[1]), "r"(a[2]), "r"(a[3]), "r"(b[0]), "r"(b[1]));
}
__device__ __forceinline__ void cpa(unsigned d, const float* s){
    asm volatile("cp.async.cg.shared.global [%0], [%1], 16;"::"r"(d),"l"(s));
}
#define CPA_COMMIT() asm volatile("cp.async.commit_group;" ::: "memory")
#define CPA_WAIT1()  asm volatile("cp.async.wait_group 1;" ::: "memory")
#define CPA_WAIT0()  asm volatile("cp.async.wait_group 0;" ::: "memory")

// smem layout (floats): stage s: A(128x36=4608) then B(4608 region)
#define AST 4608
#define STG 9216
#define AUXF 18432
#define SMEMB ((AUXF + 512) * 4)   // 75776 B

// -------- fills (cp.async, 256 threads) --------
// [row 0..127][k 0..31], row stride 36
__device__ __forceinline__ void fillT36(unsigned dst, const float* src, size_t stride, int tid){
    #pragma unroll
    for (int s = 0; s < 4; s++){
        int idx = tid + 256*s;
        int row = idx >> 3, kq = idx & 7;
        cpa(dst + (unsigned)(row*36 + 4*kq)*4u, src + (size_t)row*stride + 4*kq);
    }
}
// [k 0..31][n 0..127], row stride 136
__device__ __forceinline__ void fillKN(unsigned dst, const float* src, size_t stride, int tid){
    #pragma unroll
    for (int s = 0; s < 4; s++){
        int idx = tid + 256*s;
        int k = idx >> 5, nq = idx & 31;
        cpa(dst + (unsigned)(k*136 + 4*nq)*4u, src + (size_t)k*stride + 4*nq);
    }
}

// -------- 16 MMAs per BK=32 stage; warp tile 32x64 --------
// BKN=0: B stored [n][k] stride36; BKN=1: B stored [k][n] stride136
template<int BKN>
__device__ __forceinline__ void mma_stage(const float* As, const float* Bs,
        float acc[2][8][4], int wm, int wn, int lane){
    const int lq = lane & 3, lr = lane >> 2;
    #pragma unroll
    for (int kk = 0; kk < 4; kk++){
        const int k0 = kk*8 + lq;
        unsigned a[2][4], bf[8][2];
        #pragma unroll
        for (int i = 0; i < 2; i++){
            int mr = wm*32 + i*16 + lr;
            a[i][0] = __float_as_uint(As[mr*36 + k0]);
            a[i][1] = __float_as_uint(As[(mr+8)*36 + k0]);
            a[i][2] = __float_as_uint(As[mr*36 + k0 + 4]);
            a[i][3] = __float_as_uint(As[(mr+8)*36 + k0 + 4]);
        }
        #pragma unroll
        for (int j = 0; j < 8; j++){
            int nc = wn*64 + j*8 + lr;
            if (BKN == 0){
                bf[j][0] = __float_as_uint(Bs[nc*36 + k0]);
                bf[j][1] = __float_as_uint(Bs[nc*36 + k0 + 4]);
            } else {
                bf[j][0] = __float_as_uint(Bs[k0*136 + nc]);
                bf[j][1] = __float_as_uint(Bs[(k0+4)*136 + nc]);
            }
        }
        #pragma unroll
        for (int i = 0; i < 2; i++)
            #pragma unroll
            for (int j = 0; j < 8; j++)
                mma_tf32(acc[i][j], a[i], bf[j]);
    }
}

__global__ void zero_kernel(){
    const int total = NB*NM + NB*NC + NB*NC*NM;
    for (int i = blockIdx.x*blockDim.x + threadIdx.x; i < total; i += gridDim.x*blockDim.x){
        if (i < NB*NM) g_Ksum[i] = 0.f;
        else if (i < NB*NM + NB*NC) g_vsum[i - NB*NM] = 0.f;
        else g_matT[i - NB*NM - NB*NC] = 0.f;
    }
}

// ========== GEMM1: QKV + fused bias/norms/Ksum/vsum ==========
// grid (4 mt, 128 nblk, 8 b), 256 thr
__global__ __launch_bounds__(256, 2) void gemm_qkv(
    const float* __restrict__ x,
    const float* __restrict__ Wq, const float* __restrict__ bq,
    const float* __restrict__ Wk, const float* __restrict__ bk,
    const float* __restrict__ Wv, const float* __restrict__ bv)
{
    extern __shared__ float smf[];
    const unsigned sb = smem_u32(smf);
    const int mt = blockIdx.x, nblk = blockIdx.y, b = blockIdx.z;
    const int tid = threadIdx.x, lane = tid & 31, wid = tid >> 5;
    const int wm = wid & 3, wn = wid >> 2;
    const int n0 = nblk * 128;

    const float *W, *biasp;
    if (mt == 0)      { W = Wq;                       biasp = bq; }
    else if (mt == 1) { W = Wk;                       biasp = bk; }
    else              { W = Wv + (size_t)(mt-2)*128*NC; biasp = bv + (mt-2)*128; }
    const float* xb = x + (size_t)b*NC*NPIX + n0;

    float acc[2][8][4] = {};

    fillT36(sb, W, NC, tid);
    fillKN(sb + AST*4, xb, NPIX, tid);
    CPA_COMMIT();
    for (int it = 0; it < 8; ++it){
        const int cur = it & 1;
        if (it + 1 < 8){
            const int nx = (it+1) & 1, kt = (it+1)*32;
            fillT36(sb + nx*STG*4, W + kt, NC, tid);
            fillKN(sb + (nx*STG + AST)*4, xb + (size_t)kt*NPIX, NPIX, tid);
            CPA_COMMIT(); CPA_WAIT1();
        } else CPA_WAIT0();
        __syncthreads();
        mma_stage<1>(smf + cur*STG, smf + cur*STG + AST, acc, wm, wn, lane);
        __syncthreads();
    }

    // ---- epilogue: bias -> Tile[128][129]; norms; coalesced store; Ksum/vsum ----
    float* Tile = smf;
    float* sred = smf + AUXF;
    const int lq = lane & 3, lr = lane >> 2;
    #pragma unroll
    for (int i = 0; i < 2; i++){
        int r = wm*32 + i*16 + lr;
        float bA = biasp[r], bB = biasp[r+8];
        #pragma unroll
        for (int j = 0; j < 8; j++){
            int c = wn*64 + j*8 + 2*lq;
            Tile[r*129 + c]       = acc[i][j][0] + bA;
            Tile[r*129 + c + 1]   = acc[i][j][1] + bA;
            Tile[(r+8)*129 + c]   = acc[i][j][2] + bB;
            Tile[(r+8)*129 + c+1] = acc[i][j][3] + bB;
        }
    }
    __syncthreads();
    if (mt < 2 && tid < 128){
        float s = 0.f;
        #pragma unroll 16
        for (int r = 0; r < 128; r++){ float v = Tile[r*129 + tid]; s = fmaf(v, v, s); }
        sred[tid] = rsqrtf(s);
    }
    __syncthreads();
    float* outp = g_QKV + ((size_t)b*512 + (size_t)mt*128)*NPIX + n0;
    {
        const int col = tid & 127, hf = tid >> 7;
        const float sc = (mt < 2) ? sred[col] : 1.f;
        #pragma unroll 8
        for (int rr = 0; rr < 64; rr++){
            int r = hf*64 + rr;
            outp[(size_t)r*NPIX + col] = Tile[r*129 + col] * sc;
        }
    }
    if (mt >= 1 && tid < 128){
        float s = 0.f;
        if (mt == 1){
            #pragma unroll 16
            for (int c = 0; c < 128; c++) s = fmaf(Tile[tid*129 + c], sred[c], s);
            atomicAdd(&g_Ksum[b*NM + tid], s);
        } else {
            #pragma unroll 16
            for (int c = 0; c < 128; c++) s += Tile[tid*129 + c];
            atomicAdd(&g_vsum[b*NC + (mt-2)*128 + tid], s);
        }
    }
}

// ========== GEMM2: matT[c][m] += V @ Kn^T (split-K over pixels) ==========
// grid (32 chunks, 2 ch, 8 b), 256 thr; 512 pixels/block = 16 stages
__global__ __launch_bounds__(256, 2) void gemm_kv(){
    extern __shared__ float smf[];
    const unsigned sb = smem_u32(smf);
    const int chunk = blockIdx.x, ch = blockIdx.y, b = blockIdx.z;
    const int tid = threadIdx.x, lane = tid & 31, wid = tid >> 5;
    const int wm = wid & 3, wn = wid >> 2;
    const int n0 = chunk * 512;

    const float* Va = g_QKV + ((size_t)b*512 + 256 + (size_t)ch*128)*NPIX + n0;
    const float* Kn = g_QKV + ((size_t)b*512 + 128)*NPIX + n0;

    float acc[2][8][4] = {};
    fillT36(sb, Va, NPIX, tid);
    fillT36(sb + AST*4, Kn, NPIX, tid);
    CPA_COMMIT();
    for (int it = 0; it < 16; ++it){
        const int cur = it & 1;
        if (it + 1 < 16){
            const int nx = (it+1) & 1, kt = (it+1)*32;
            fillT36(sb + nx*STG*4, Va + kt, NPIX, tid);
            fillT36(sb + (nx*STG + AST)*4, Kn + kt, NPIX, tid);
            CPA_COMMIT(); CPA_WAIT1();
        } else CPA_WAIT0();
        __syncthreads();
        mma_stage<0>(smf + cur*STG, smf + cur*STG + AST, acc, wm, wn, lane);
        __syncthreads();
    }

    // D[c][m] -> atomics into g_matT[b][ch*128+c][m]
    const int lq = lane & 3, lr = lane >> 2;
    #pragma unroll
    for (int i = 0; i < 2; i++){
        int r = wm*32 + i*16 + lr;
        float* m0 = g_matT + ((size_t)b*NC + ch*128 + r)*NM;
        float* m1 = m0 + 8*NM;
        #pragma unroll
        for (int j = 0; j < 8; j++){
            int c = wn*64 + j*8 + 2*lq;
            atomicAdd(&m0[c],   acc[i][j][0]);
            atomicAdd(&m0[c+1], acc[i][j][1]);
            atomicAdd(&m1[c],   acc[i][j][2]);
            atomicAdd(&m1[c+1], acc[i][j][3]);
        }
    }
}

// ---------------- tailor[n] = 1/(N + Qn . (Ksum + eps)) ----------------
__global__ void tailor_kernel(){
    __shared__ float ks[128];
    const int b = blockIdx.y;
    const int n = blockIdx.x * 256 + threadIdx.x;
    if (threadIdx.x < 128) ks[threadIdx.x] = g_Ksum[b*NM + threadIdx.x] + EPSV;
    __syncthreads();
    const float* Qb = g_QKV + (size_t)b*512*NPIX;
    float dot = 0.f;
    #pragma unroll 8
    for (int c = 0; c < NM; c++)
        dot = fmaf(Qb[(size_t)c*NPIX + n], ks[c], dot);
    g_tailor[b*NPIX + n] = 1.0f / ((float)NPIX + dot);
}

// ========== GEMM3: out[c][n] = g*tailor[n]*(vsum[c] + matT @ Qn) ==========
// grid (128 nblk, 2 ch, 8 b), 256 thr; K=128 -> 4 stages
__global__ __launch_bounds__(256, 2) void gemm_out(
    const float* __restrict__ gamma, float* __restrict__ out)
{
    extern __shared__ float smf[];
    const unsigned sb = smem_u32(smf);
    const int nblk = blockIdx.x, ch = blockIdx.y, b = blockIdx.z;
    const int tid = threadIdx.x, lane = tid & 31, wid = tid >> 5;
    const int wm = wid & 3, wn = wid >> 2;
    const int n0 = nblk * 128;

    float* stl = smf + AUXF;        // 128
    float* svs = stl + 128;         // 128
    if (tid < 128){
        stl[tid] = gamma[0] * g_tailor[b*NPIX + n0 + tid];
        svs[tid] = g_vsum[b*NC + ch*128 + tid];
    }

    const float* mA = g_matT + ((size_t)b*NC + ch*128)*NM;
    const float* Qb = g_QKV + (size_t)b*512*NPIX + n0;

    float acc[2][8][4] = {};
    fillT36(sb, mA, NM, tid);
    fillKN(sb + AST*4, Qb, NPIX, tid);
    CPA_COMMIT();
    for (int it = 0; it < 4; ++it){
        const int cur = it & 1;
        if (it + 1 < 4){
            const int nx = (it+1) & 1, kt = (it+1)*32;
            fillT36(sb + nx*STG*4, mA + kt, NM, tid);
            fillKN(sb + (nx*STG + AST)*4, Qb + (size_t)kt*NPIX, NPIX, tid);
            CPA_COMMIT(); CPA_WAIT1();
        } else CPA_WAIT0();
        __syncthreads();
        mma_stage<1>(smf + cur*STG, smf + cur*STG + AST, acc, wm, wn, lane);
        __syncthreads();
    }

    const int lq = lane & 3, lr = lane >> 2;
    float* ob = out + ((size_t)b*NC + (size_t)ch*128)*NPIX + n0;
    #pragma unroll
    for (int i = 0; i < 2; i++){
        int r = wm*32 + i*16 + lr;
        float v0 = svs[r], v1 = svs[r+8];
        #pragma unroll
        for (int j = 0; j < 8; j++){
            int c = wn*64 + j*8 + 2*lq;
            float t0 = stl[c], t1 = stl[c+1];
            *reinterpret_cast<float2*>(&ob[(size_t)r*NPIX + c]) =
                make_float2(t0*(v0 + acc[i][j][0]), t1*(v0 + acc[i][j][1]));
            *reinterpret_cast<float2*>(&ob[(size_t)(r+8)*NPIX + c]) =
                make_float2(t0*(v1 + acc[i][j][2]), t1*(v1 + acc[i][j][3]));
        }
    }
}

// ---------------- launch ----------------
extern "C" void kernel_launch(void* const* d_in, const int* in_sizes, int n_in,
                              void* d_out, int out_size)
{
    const float* x     = (const float*)d_in[0];
    const float* Wq    = (const float*)d_in[1];
    const float* bq    = (const float*)d_in[2];
    const float* Wk    = (const float*)d_in[3];
    const float* bk    = (const float*)d_in[4];
    const float* Wv    = (const float*)d_in[5];
    const float* bv    = (const float*)d_in[6];
    const float* gamma = (const float*)d_in[7];
    float* out = (float*)d_out;

    static bool attr_done = false;
    if (!attr_done){
        cudaFuncSetAttribute(gemm_qkv, cudaFuncAttributeMaxDynamicSharedMemorySize, SMEMB);
        cudaFuncSetAttribute(gemm_kv,  cudaFuncAttributeMaxDynamicSharedMemorySize, SMEMB);
        cudaFuncSetAttribute(gemm_out, cudaFuncAttributeMaxDynamicSharedMemorySize, SMEMB);
        attr_done = true;
    }

    zero_kernel<<<128, 256>>>();
    gemm_qkv<<<dim3(4, 128, NB), 256, SMEMB>>>(x, Wq, bq, Wk, bk, Wv, bv);
    gemm_kv<<<dim3(32, 2, NB), 256, SMEMB>>>();
    tailor_kernel<<<dim3(NPIX/256, NB), 256>>>();
    gemm_out<<<dim3(128, 2, NB), 256, SMEMB>>>(gamma, out);
}